// round 14
// baseline (speedup 1.0000x reference)
#include <cuda_runtime.h>

#define NRAYS 131072
#define RPB 16           // rays per block (2 per warp, 16-lane segments)
#define FULL 0xffffffffu

__device__ __forceinline__ float tanh_approx(float x) {
    float y;
    asm("tanh.approx.f32 %0, %1;" : "=f"(y) : "f"(x));
    return y;
}
// sigmoid(2*xh) = 0.5*tanh(xh)+0.5 ; caller passes the pre-halved logit
__device__ __forceinline__ float sigmoid_h(float xh) {
    return fmaf(0.5f, tanh_approx(xh), 0.5f);
}
__device__ __forceinline__ float ex2(float x) {
    float y;
    asm("ex2.approx.f32 %0, %1;" : "=f"(y) : "f"(x));
    return y;
}
// dens2 = softplus(x)*log2e = log2(1+e^x), branchless select (no divergence)
__device__ __forceinline__ float softplus_lg2(float x) {
    float y = __expf(-fabsf(x));
    float ser = y * fmaf(y, fmaf(y, fmaf(-0.36067376f, y, 0.48089835f),
                                 -0.72134752f), 1.44269504f);
    float big = __log2f(1.0f + y);
    float l2 = (y < 0.03125f) ? ser : big;
    return fmaf(fmaxf(x, 0.0f), 1.44269504f, l2);
}
// coarse grid value, exact same floats as reference linspace
__device__ __forceinline__ float t_of_i(int i) {
    float x = (i == 63) ? 1.0f : (float)i * (1.0f / 63.0f);
    return fmaf(4.0f, x, 2.0f);
}
// u grid, exact same floats as reference linspace
__device__ __forceinline__ float u_of(int k) {
    return (k == 63) ? 1.0f : (float)k * (1.0f / 63.0f);
}

// count of c[i] <= u over exactly 64 sorted entries (result in [0,64])
__device__ __forceinline__ int cnt64_le(const float* c, float u) {
    if (c[63] <= u) return 64;
    int pos = 0;
#pragma unroll
    for (int step = 32; step >= 1; step >>= 1)
        if (c[pos + step - 1] <= u) pos += step;
    return pos;
}
// count of c[i] < v over exactly 64 sorted entries (result in [0,64])
// Comparison on the ACTUAL stored floats -> merge ranks always form a
// permutation (the round-13 analytic-duality shortcut violated this).
__device__ __forceinline__ int cnt64_lt(const float* c, float v) {
    if (c[63] < v) return 64;
    int pos = 0;
#pragma unroll
    for (int step = 32; step >= 1; step >>= 1)
        if (c[pos + step - 1] < v) pos += step;
    return pos;
}
// count of {i in [0,64): t_of_i(i) <= v}  -- analytic guess + exact correction
// (safe: compares against the exact t_of_i floats themselves)
__device__ __forceinline__ int cnt_ta_le(float v) {
    float g = fmaf(v, 15.75f, -31.5f);     // (v-2)*63/4
    int c = (int)floorf(g) + 1;
    c = min(64, max(0, c));
    if (c < 64 && t_of_i(c) <= v) c++;
    if (c < 64 && t_of_i(c) <= v) c++;
    if (c > 0 && t_of_i(c - 1) > v) c--;
    if (c > 0 && t_of_i(c - 1) > v) c--;
    return c;
}
// reduce-sum within a 16-lane segment (xor d<16 never crosses segments)
__device__ __forceinline__ float seg_red_sum(float x) {
#pragma unroll
    for (int d = 8; d >= 1; d >>= 1) x += __shfl_xor_sync(FULL, x, d);
    return x;
}

__global__ void __launch_bounds__(256, 7) vr_kernel(
    const float* __restrict__ ro, const float* __restrict__ rd,
    const float* __restrict__ Wd, const float* __restrict__ Wc,
    float* __restrict__ out)
{
    const int tid = threadIdx.x;
    const int s = tid & 15;              // sub-lane within segment
    const int seg = tid >> 4;            // segment (ray) index within block
    const int ray = blockIdx.x * RPB + seg;

    __shared__ float s_ts[RPB][64];
    __shared__ float s_cdf[RPB][65];
    __shared__ __align__(16) float s_ft[RPB][132];

    float* ts = s_ts[seg];
    float* cdf = s_cdf[seg];
    float* ft = s_ft[seg];

    // ---- per-ray precompute: pos @ W = (ro.W) + t*(rd.W) ----
    const float ox = ro[3 * ray + 0], oy = ro[3 * ray + 1], oz = ro[3 * ray + 2];
    const float dx = rd[3 * ray + 0], dy = rd[3 * ray + 1], dz = rd[3 * ray + 2];
    const float wd0 = __ldg(&Wd[0]), wd1 = __ldg(&Wd[1]), wd2 = __ldg(&Wd[2]);
    const float ad = ox * wd0 + oy * wd1 + oz * wd2;
    const float bd = dx * wd0 + dy * wd1 + dz * wd2;
    float ach[3], bch[3];   // PRE-HALVED color coefficients for tanh-sigmoid
#pragma unroll
    for (int k = 0; k < 3; k++) {
        float w0 = __ldg(&Wc[k]), w1 = __ldg(&Wc[3 + k]), w2 = __ldg(&Wc[6 + k]);
        ach[k] = 0.5f * (ox * w0 + oy * w1 + oz * w2);
        bch[k] = 0.5f * (dx * w0 + dy * w1 + dz * w2);
    }

    // ========= COARSE PASS: 4 samples/lane, local-accumulate =========
    float t_c[4], localw[4];
    float trans_l = 1.0f;
    float lsr = 0.f, lsg = 0.f, lsb = 0.f, lsd = 0.f, lsa = 0.f;
#pragma unroll
    for (int c = 0; c < 4; c++) {
        int i = 4 * s + c;
        float t = t_of_i(i);
        t_c[c] = t;
        float dist = (i < 63) ? (t_of_i(i + 1) - t) : 1e10f;
        float dens2 = softplus_lg2(fmaf(t, bd, ad));
        float a = 1.0f - ex2(-dens2 * dist);
        float f = (1.0f - a) + 1e-10f;
        float wl = a * trans_l;
        localw[c] = wl;
        float cr = sigmoid_h(fmaf(t, bch[0], ach[0]));
        float cg = sigmoid_h(fmaf(t, bch[1], ach[1]));
        float cb = sigmoid_h(fmaf(t, bch[2], ach[2]));
        lsr += wl * cr; lsg += wl * cg; lsb += wl * cb;
        lsd += wl * t;  lsa += wl;
        trans_l *= f;
    }
    // segmented exclusive product scan of per-lane transmittance
    float S = trans_l;
#pragma unroll
    for (int d = 1; d < 16; d <<= 1) {
        float v = __shfl_up_sync(FULL, S, d, 16);
        if (s >= d) S *= v;
    }
    float E = __shfl_up_sync(FULL, S, 1, 16);
    if (s == 0) E = 1.0f;

    float sr = E * lsr, sg = E * lsg, sb = E * lsb, sd = E * lsd, sa = E * lsa;
    sr = seg_red_sum(sr); sg = seg_red_sum(sg); sb = seg_red_sum(sb);
    sd = seg_red_sum(sd); sa = seg_red_sum(sa);

    // ---- CDF ----
    float ps0 = E * localw[0] + 1e-5f;
    float ps1 = ps0 + (E * localw[1] + 1e-5f);
    float ps2 = ps1 + (E * localw[2] + 1e-5f);
    float ps3 = ps2 + (E * localw[3] + 1e-5f);
    float Ss = ps3;
#pragma unroll
    for (int d = 1; d < 16; d <<= 1) {
        float v = __shfl_up_sync(FULL, Ss, d, 16);
        if (s >= d) Ss += v;
    }
    float Es = __shfl_up_sync(FULL, Ss, 1, 16);
    if (s == 0) Es = 0.0f;
    float total = __shfl_sync(FULL, Ss, 15, 16);
    float inv_total = __fdividef(1.0f, total);
    if (s == 0) cdf[0] = 0.0f;
    cdf[4 * s + 1] = (Es + ps0) * inv_total;
    cdf[4 * s + 2] = (Es + ps1) * inv_total;
    cdf[4 * s + 3] = (Es + ps2) * inv_total;
    cdf[4 * s + 4] = (Es + ps3) * inv_total;
    __syncwarp();

    // ---- inverse-CDF importance sampling (4 u's / lane) ----
    float tsv[4];
#pragma unroll
    for (int c = 0; c < 4; c++) {
        int k = 4 * s + c;
        float u = u_of(k);
        int idx = 1 + cnt64_le(cdf + 1, u);   // searchsorted 'right' over 65 entries
        int below = idx - 1;
        int above = (idx < 64) ? idx : 64;
        float cdf0 = cdf[below];
        float cdf1 = cdf[above];
        float bin0 = t_of_i((below < 63) ? below : 63);
        float bin1 = t_of_i((above < 63) ? above : 63);
        float denom = cdf1 - cdf0;
        if (denom < 1e-5f) denom = 1.0f;
        float tt = __fdividef(u - cdf0, denom);
        float v = fmaf(tt, bin1 - bin0, bin0);
        tsv[c] = v;
        ts[k] = v;
    }
    __syncwarp();

    // ---- merge ranks (exact comparisons on stored floats) -> scatter to ft ----
#pragma unroll
    for (int c = 0; c < 4; c++) {
        int j = 4 * s + c;
        float av = t_c[c];
        ft[j + cnt64_lt(ts, av)] = av;      // a before equal b
        float bv = tsv[c];
        ft[j + cnt_ta_le(bv)] = bv;
    }
    __syncwarp();

    // ========= FINE PASS: 8 samples/lane, local-accumulate =========
    const float4 q1 = *reinterpret_cast<const float4*>(&ft[8 * s]);
    const float4 q2 = *reinterpret_cast<const float4*>(&ft[8 * s + 4]);
    const float t9 = ft[8 * s + 8];   // s==15: garbage, guarded by i<127
    float tf[9] = {q1.x, q1.y, q1.z, q1.w, q2.x, q2.y, q2.z, q2.w, t9};

    float ltr = 1.0f;
    float lfr = 0.f, lfg = 0.f, lfb = 0.f, lfd = 0.f, lfa = 0.f;
#pragma unroll
    for (int c = 0; c < 8; c++) {
        int i = 8 * s + c;
        float t = tf[c];
        float dist = (i < 127) ? (tf[c + 1] - t) : 1e10f;
        float dens2 = softplus_lg2(fmaf(t, bd, ad));
        float a = 1.0f - ex2(-dens2 * dist);
        float f = (1.0f - a) + 1e-10f;
        float wl = a * ltr;
        float cr = sigmoid_h(fmaf(t, bch[0], ach[0]));
        float cg = sigmoid_h(fmaf(t, bch[1], ach[1]));
        float cb = sigmoid_h(fmaf(t, bch[2], ach[2]));
        lfr += wl * cr; lfg += wl * cg; lfb += wl * cb;
        lfd += wl * t;  lfa += wl;
        ltr *= f;
    }
    float Sf = ltr;
#pragma unroll
    for (int d = 1; d < 16; d <<= 1) {
        float v = __shfl_up_sync(FULL, Sf, d, 16);
        if (s >= d) Sf *= v;
    }
    float Ef = __shfl_up_sync(FULL, Sf, 1, 16);
    if (s == 0) Ef = 1.0f;

    float fsr = Ef * lfr, fsg = Ef * lfg, fsb = Ef * lfb;
    float fsd = Ef * lfd, fsa = Ef * lfa;
    fsr = seg_red_sum(fsr); fsg = seg_red_sum(fsg); fsb = seg_red_sum(fsb);
    fsd = seg_red_sum(fsd); fsa = seg_red_sum(fsa);

    // ---- outputs: rgb(3N), depth(N), acc(N), frgb(3N), fdepth(N), facc(N) ----
    if (s == 0) {
        const int N = NRAYS;
        float bgc = 1.0f - sa;
        out[3 * ray + 0] = sr + bgc;
        out[3 * ray + 1] = sg + bgc;
        out[3 * ray + 2] = sb + bgc;
        out[3 * N + ray] = sd;
        out[4 * N + ray] = sa;
        float fbgc = 1.0f - fsa;
        out[5 * N + 3 * ray + 0] = fsr + fbgc;
        out[5 * N + 3 * ray + 1] = fsg + fbgc;
        out[5 * N + 3 * ray + 2] = fsb + fbgc;
        out[8 * N + ray] = fsd;
        out[9 * N + ray] = fsa;
    }
}

extern "C" void kernel_launch(void* const* d_in, const int* in_sizes, int n_in,
                              void* d_out, int out_size) {
    const float* ro = nullptr;
    const float* rd = nullptr;
    const float* Wd = nullptr;
    const float* Wc = nullptr;
    for (int i = 0; i < n_in; i++) {
        int sz = in_sizes[i];
        if (sz == 3) Wd = (const float*)d_in[i];
        else if (sz == 9) Wc = (const float*)d_in[i];
        else if (sz == 3 * NRAYS) {
            if (!ro) ro = (const float*)d_in[i];
            else if (!rd) rd = (const float*)d_in[i];
        }
    }
    vr_kernel<<<NRAYS / RPB, 256>>>(ro, rd, Wd, Wc, (float*)d_out);
}

// round 15
// speedup vs baseline: 1.0807x; 1.0807x over previous
#include <cuda_runtime.h>

#define NRAYS 131072
#define RPB 16           // rays per block (2 per warp, 16-lane segments)
#define FULL 0xffffffffu

__device__ __forceinline__ float tanh_approx(float x) {
    float y;
    asm("tanh.approx.f32 %0, %1;" : "=f"(y) : "f"(x));
    return y;
}
__device__ __forceinline__ float ex2(float x) {
    float y;
    asm("ex2.approx.f32 %0, %1;" : "=f"(y) : "f"(x));
    return y;
}
// dens2 = softplus(x)*log2e = log2(1+e^x), branchless select (no divergence)
__device__ __forceinline__ float softplus_lg2(float x) {
    float y = __expf(-fabsf(x));
    float ser = y * fmaf(y, fmaf(y, fmaf(-0.36067376f, y, 0.48089835f),
                                 -0.72134752f), 1.44269504f);
    float big = __log2f(1.0f + y);
    float l2 = (y < 0.03125f) ? ser : big;
    return fmaf(fmaxf(x, 0.0f), 1.44269504f, l2);
}
// coarse grid value. NOTE: no i==63 special case needed — fl(63*fl(1/63))
// rounds to exactly 1.0f (31*2^-29 < 2^-24), so this is bit-identical to
// the guarded linspace for all i in [0,63].
__device__ __forceinline__ float t_of_i(int i) {
    return fmaf(4.0f, (float)i * (1.0f / 63.0f), 2.0f);
}
// u grid, same argument: unconditional form is exact for k in [0,63]
__device__ __forceinline__ float u_of(int k) {
    return (float)k * (1.0f / 63.0f);
}

// count of c[i] <= u over exactly 64 sorted entries (result in [0,64])
__device__ __forceinline__ int cnt64_le(const float* c, float u) {
    if (c[63] <= u) return 64;
    int pos = 0;
#pragma unroll
    for (int step = 32; step >= 1; step >>= 1)
        if (c[pos + step - 1] <= u) pos += step;
    return pos;
}
// count of c[i] < v over exactly 64 sorted entries (result in [0,64])
// Comparison on the ACTUAL stored floats -> merge ranks form a permutation.
__device__ __forceinline__ int cnt64_lt(const float* c, float v) {
    if (c[63] < v) return 64;
    int pos = 0;
#pragma unroll
    for (int step = 32; step >= 1; step >>= 1)
        if (c[pos + step - 1] < v) pos += step;
    return pos;
}
// count of {i in [0,64): t_of_i(i) <= v}  -- analytic guess + exact correction
__device__ __forceinline__ int cnt_ta_le(float v) {
    float g = fmaf(v, 15.75f, -31.5f);     // (v-2)*63/4
    int c = (int)floorf(g) + 1;
    c = min(64, max(0, c));
    if (c < 64 && t_of_i(c) <= v) c++;
    if (c < 64 && t_of_i(c) <= v) c++;
    if (c > 0 && t_of_i(c - 1) > v) c--;
    if (c > 0 && t_of_i(c - 1) > v) c--;
    return c;
}
// reduce-sum within a 16-lane segment (xor d<16 never crosses segments)
__device__ __forceinline__ float seg_red_sum(float x) {
#pragma unroll
    for (int d = 8; d >= 1; d >>= 1) x += __shfl_xor_sync(FULL, x, d);
    return x;
}

__global__ void __launch_bounds__(256, 6) vr_kernel(
    const float* __restrict__ ro, const float* __restrict__ rd,
    const float* __restrict__ Wd, const float* __restrict__ Wc,
    float* __restrict__ out)
{
    const int tid = threadIdx.x;
    const int s = tid & 15;              // sub-lane within segment
    const int seg = tid >> 4;            // segment (ray) index within block
    const int ray = blockIdx.x * RPB + seg;

    __shared__ float s_ts[RPB][64];
    __shared__ float s_cdf[RPB][65];
    __shared__ __align__(16) float s_ft[RPB][132];

    float* ts = s_ts[seg];
    float* cdf = s_cdf[seg];
    float* ft = s_ft[seg];

    // ---- per-ray precompute: pos @ W = (ro.W) + t*(rd.W) ----
    const float ox = ro[3 * ray + 0], oy = ro[3 * ray + 1], oz = ro[3 * ray + 2];
    const float dx = rd[3 * ray + 0], dy = rd[3 * ray + 1], dz = rd[3 * ray + 2];
    const float wd0 = __ldg(&Wd[0]), wd1 = __ldg(&Wd[1]), wd2 = __ldg(&Wd[2]);
    const float ad = ox * wd0 + oy * wd1 + oz * wd2;
    const float bd = dx * wd0 + dy * wd1 + dz * wd2;
    float ach[3], bch[3];   // PRE-HALVED color coefficients for tanh-sigmoid
#pragma unroll
    for (int k = 0; k < 3; k++) {
        float w0 = __ldg(&Wc[k]), w1 = __ldg(&Wc[3 + k]), w2 = __ldg(&Wc[6 + k]);
        ach[k] = 0.5f * (ox * w0 + oy * w1 + oz * w2);
        bch[k] = 0.5f * (dx * w0 + dy * w1 + dz * w2);
    }

    // ========= COARSE PASS: 4 samples/lane, local-accumulate =========
    // colors accumulated as wl*tanh (affine 0.5x+0.5 deferred to output)
    float t_c[5], localw[4];
#pragma unroll
    for (int c = 0; c < 5; c++) t_c[c] = t_of_i(4 * s + c);  // i=64 unused
    float trans_l = 1.0f;
    float lsr = 0.f, lsg = 0.f, lsb = 0.f, lsd = 0.f, lsa = 0.f;
#pragma unroll
    for (int c = 0; c < 4; c++) {
        int i = 4 * s + c;
        float t = t_c[c];
        float dist = (i < 63) ? (t_c[c + 1] - t) : 1e10f;
        float dens2 = softplus_lg2(fmaf(t, bd, ad));
        float e = ex2(-dens2 * dist);
        float a = 1.0f - e;
        float f = e + 1e-10f;
        float wl = a * trans_l;
        localw[c] = wl;
        float tr = tanh_approx(fmaf(t, bch[0], ach[0]));
        float tg = tanh_approx(fmaf(t, bch[1], ach[1]));
        float tb = tanh_approx(fmaf(t, bch[2], ach[2]));
        lsr += wl * tr; lsg += wl * tg; lsb += wl * tb;
        lsd += wl * t;  lsa += wl;
        trans_l *= f;
    }
    // segmented exclusive product scan of per-lane transmittance
    float S = trans_l;
#pragma unroll
    for (int d = 1; d < 16; d <<= 1) {
        float v = __shfl_up_sync(FULL, S, d, 16);
        if (s >= d) S *= v;
    }
    float E = __shfl_up_sync(FULL, S, 1, 16);
    if (s == 0) E = 1.0f;

    float sr = seg_red_sum(E * lsr);
    float sg = seg_red_sum(E * lsg);
    float sb = seg_red_sum(E * lsb);
    float sd = seg_red_sum(E * lsd);
    float sa = seg_red_sum(E * lsa);

    // ---- CDF ----
    float ps0 = E * localw[0] + 1e-5f;
    float ps1 = ps0 + (E * localw[1] + 1e-5f);
    float ps2 = ps1 + (E * localw[2] + 1e-5f);
    float ps3 = ps2 + (E * localw[3] + 1e-5f);
    float Ss = ps3;
#pragma unroll
    for (int d = 1; d < 16; d <<= 1) {
        float v = __shfl_up_sync(FULL, Ss, d, 16);
        if (s >= d) Ss += v;
    }
    float Es = __shfl_up_sync(FULL, Ss, 1, 16);
    if (s == 0) Es = 0.0f;
    float total = __shfl_sync(FULL, Ss, 15, 16);
    float inv_total = __fdividef(1.0f, total);
    if (s == 0) cdf[0] = 0.0f;
    cdf[4 * s + 1] = (Es + ps0) * inv_total;
    cdf[4 * s + 2] = (Es + ps1) * inv_total;
    cdf[4 * s + 3] = (Es + ps2) * inv_total;
    cdf[4 * s + 4] = (Es + ps3) * inv_total;
    __syncwarp();

    // ---- inverse-CDF importance sampling (4 u's / lane) ----
    float tsv[4];
#pragma unroll
    for (int c = 0; c < 4; c++) {
        int k = 4 * s + c;
        float u = u_of(k);
        int idx = 1 + cnt64_le(cdf + 1, u);   // searchsorted 'right' over 65 entries
        int below = idx - 1;
        int above = (idx < 64) ? idx : 64;
        float cdf0 = cdf[below];
        float cdf1 = cdf[above];
        float bin0 = t_of_i((below < 63) ? below : 63);
        float bin1 = t_of_i((above < 63) ? above : 63);
        float denom = cdf1 - cdf0;
        if (denom < 1e-5f) denom = 1.0f;
        float tt = __fdividef(u - cdf0, denom);
        float v = fmaf(tt, bin1 - bin0, bin0);
        tsv[c] = v;
        ts[k] = v;
    }
    __syncwarp();

    // ---- merge ranks (exact comparisons on stored floats) -> scatter to ft ----
#pragma unroll
    for (int c = 0; c < 4; c++) {
        int j = 4 * s + c;
        float av = t_c[c];
        ft[j + cnt64_lt(ts, av)] = av;      // a before equal b
        float bv = tsv[c];
        ft[j + cnt_ta_le(bv)] = bv;
    }
    __syncwarp();

    // ========= FINE PASS: 8 samples/lane, local-accumulate =========
    const float4 q1 = *reinterpret_cast<const float4*>(&ft[8 * s]);
    const float4 q2 = *reinterpret_cast<const float4*>(&ft[8 * s + 4]);
    const float t9 = ft[8 * s + 8];   // s==15: garbage, guarded by i<127
    float tf[9] = {q1.x, q1.y, q1.z, q1.w, q2.x, q2.y, q2.z, q2.w, t9};

    float ltr = 1.0f;
    float lfr = 0.f, lfg = 0.f, lfb = 0.f, lfd = 0.f, lfa = 0.f;
#pragma unroll
    for (int c = 0; c < 8; c++) {
        int i = 8 * s + c;
        float t = tf[c];
        float dist = (i < 127) ? (tf[c + 1] - t) : 1e10f;
        float dens2 = softplus_lg2(fmaf(t, bd, ad));
        float e = ex2(-dens2 * dist);
        float a = 1.0f - e;
        float f = e + 1e-10f;
        float wl = a * ltr;
        float tr = tanh_approx(fmaf(t, bch[0], ach[0]));
        float tg = tanh_approx(fmaf(t, bch[1], ach[1]));
        float tb = tanh_approx(fmaf(t, bch[2], ach[2]));
        lfr += wl * tr; lfg += wl * tg; lfb += wl * tb;
        lfd += wl * t;  lfa += wl;
        ltr *= f;
    }
    float Sf = ltr;
#pragma unroll
    for (int d = 1; d < 16; d <<= 1) {
        float v = __shfl_up_sync(FULL, Sf, d, 16);
        if (s >= d) Sf *= v;
    }
    float Ef = __shfl_up_sync(FULL, Sf, 1, 16);
    if (s == 0) Ef = 1.0f;

    float fsr = seg_red_sum(Ef * lfr);
    float fsg = seg_red_sum(Ef * lfg);
    float fsb = seg_red_sum(Ef * lfb);
    float fsd = seg_red_sum(Ef * lfd);
    float fsa = seg_red_sum(Ef * lfa);

    // ---- outputs: rgb(3N), depth(N), acc(N), frgb(3N), fdepth(N), facc(N) ----
    // color_out = 0.5*Σwl·tanh + 0.5*Σwl + (1 - Σwl) = 0.5*(sum_tanh - acc) + 1
    if (s == 0) {
        const int N = NRAYS;
        out[3 * ray + 0] = fmaf(0.5f, sr - sa, 1.0f);
        out[3 * ray + 1] = fmaf(0.5f, sg - sa, 1.0f);
        out[3 * ray + 2] = fmaf(0.5f, sb - sa, 1.0f);
        out[3 * N + ray] = sd;
        out[4 * N + ray] = sa;
        out[5 * N + 3 * ray + 0] = fmaf(0.5f, fsr - fsa, 1.0f);
        out[5 * N + 3 * ray + 1] = fmaf(0.5f, fsg - fsa, 1.0f);
        out[5 * N + 3 * ray + 2] = fmaf(0.5f, fsb - fsa, 1.0f);
        out[8 * N + ray] = fsd;
        out[9 * N + ray] = fsa;
    }
}

extern "C" void kernel_launch(void* const* d_in, const int* in_sizes, int n_in,
                              void* d_out, int out_size) {
    const float* ro = nullptr;
    const float* rd = nullptr;
    const float* Wd = nullptr;
    const float* Wc = nullptr;
    for (int i = 0; i < n_in; i++) {
        int sz = in_sizes[i];
        if (sz == 3) Wd = (const float*)d_in[i];
        else if (sz == 9) Wc = (const float*)d_in[i];
        else if (sz == 3 * NRAYS) {
            if (!ro) ro = (const float*)d_in[i];
            else if (!rd) rd = (const float*)d_in[i];
        }
    }
    vr_kernel<<<NRAYS / RPB, 256>>>(ro, rd, Wd, Wc, (float*)d_out);
}

// round 16
// speedup vs baseline: 1.1057x; 1.0232x over previous
#include <cuda_runtime.h>

#define NRAYS 131072
#define RPB 16           // rays per block (2 per warp, 16-lane segments)
#define FULL 0xffffffffu

__device__ __forceinline__ float tanh_approx(float x) {
    float y;
    asm("tanh.approx.f32 %0, %1;" : "=f"(y) : "f"(x));
    return y;
}
__device__ __forceinline__ float ex2(float x) {
    float y;
    asm("ex2.approx.f32 %0, %1;" : "=f"(y) : "f"(x));
    return y;
}
// dens2 = softplus(x)*log2e = log2(1+e^x).
// max(log2f(1+y), y*(log2e - y*log2e/2)) is tail-safe: when 1+y==1 truncates
// the log to 0 (the 7.04e-2 bug zone), the 2-term candidate is exact; in the
// band where log2f can overshoot, the terminal exponent is >>1 so alpha==1
// regardless; elsewhere log2f wins and is accurate.
__device__ __forceinline__ float softplus_lg2(float x) {
    float y = __expf(-fabsf(x));
    float cand = y * fmaf(y, -0.72134752f, 1.44269504f);
    float big = __log2f(1.0f + y);
    float l2 = fmaxf(big, cand);
    return fmaf(fmaxf(x, 0.0f), 1.44269504f, l2);
}
// coarse grid value: unconditional form is bit-identical to the guarded
// linspace for all i in [0,63] (fl(63*fl(1/63)) rounds to exactly 1.0f)
__device__ __forceinline__ float t_of_i(int i) {
    return fmaf(4.0f, (float)i * (1.0f / 63.0f), 2.0f);
}
__device__ __forceinline__ float u_of(int k) {
    return (float)k * (1.0f / 63.0f);
}

// count of c[i] <= u over exactly 64 sorted entries (result in [0,64])
__device__ __forceinline__ int cnt64_le(const float* c, float u) {
    if (c[63] <= u) return 64;
    int pos = 0;
#pragma unroll
    for (int step = 32; step >= 1; step >>= 1)
        if (c[pos + step - 1] <= u) pos += step;
    return pos;
}
// count of c[i] < v over exactly 64 sorted entries (result in [0,64])
// Comparison on the ACTUAL stored floats -> merge ranks form a permutation.
__device__ __forceinline__ int cnt64_lt(const float* c, float v) {
    if (c[63] < v) return 64;
    int pos = 0;
#pragma unroll
    for (int step = 32; step >= 1; step >>= 1)
        if (c[pos + step - 1] < v) pos += step;
    return pos;
}
// count of {i in [0,64): t_of_i(i) <= v}  -- analytic guess + exact correction
__device__ __forceinline__ int cnt_ta_le(float v) {
    float g = fmaf(v, 15.75f, -31.5f);     // (v-2)*63/4
    int c = (int)floorf(g) + 1;
    c = min(64, max(0, c));
    if (c < 64 && t_of_i(c) <= v) c++;
    if (c < 64 && t_of_i(c) <= v) c++;
    if (c > 0 && t_of_i(c - 1) > v) c--;
    if (c > 0 && t_of_i(c - 1) > v) c--;
    return c;
}
// reduce-sum within a 16-lane segment (xor d<16 never crosses segments)
__device__ __forceinline__ float seg_red_sum(float x) {
#pragma unroll
    for (int d = 8; d >= 1; d >>= 1) x += __shfl_xor_sync(FULL, x, d);
    return x;
}

__global__ void __launch_bounds__(256, 6) vr_kernel(
    const float* __restrict__ ro, const float* __restrict__ rd,
    const float* __restrict__ Wd, const float* __restrict__ Wc,
    float* __restrict__ out)
{
    const int tid = threadIdx.x;
    const int s = tid & 15;              // sub-lane within segment
    const int seg = tid >> 4;            // segment (ray) index within block
    const int ray = blockIdx.x * RPB + seg;

    __shared__ float s_ts[RPB][64];
    __shared__ float s_cdf[RPB][65];
    __shared__ __align__(16) float s_ft[RPB][132];

    float* ts = s_ts[seg];
    float* cdf = s_cdf[seg];
    float* ft = s_ft[seg];

    // ---- per-ray precompute: pos @ W = (ro.W) + t*(rd.W) ----
    const float ox = ro[3 * ray + 0], oy = ro[3 * ray + 1], oz = ro[3 * ray + 2];
    const float dx = rd[3 * ray + 0], dy = rd[3 * ray + 1], dz = rd[3 * ray + 2];
    const float wd0 = __ldg(&Wd[0]), wd1 = __ldg(&Wd[1]), wd2 = __ldg(&Wd[2]);
    const float ad = ox * wd0 + oy * wd1 + oz * wd2;
    const float bd = dx * wd0 + dy * wd1 + dz * wd2;
    float ach[3], bch[3];   // PRE-HALVED color coefficients for tanh-sigmoid
#pragma unroll
    for (int k = 0; k < 3; k++) {
        float w0 = __ldg(&Wc[k]), w1 = __ldg(&Wc[3 + k]), w2 = __ldg(&Wc[6 + k]);
        ach[k] = 0.5f * (ox * w0 + oy * w1 + oz * w2);
        bch[k] = 0.5f * (dx * w0 + dy * w1 + dz * w2);
    }

    // ========= COARSE PASS: 4 samples/lane, local-accumulate =========
    float t_c[4], localw[4];
#pragma unroll
    for (int c = 0; c < 4; c++) t_c[c] = t_of_i(4 * s + c);
    float trans_l = 1.0f;
    float lsr = 0.f, lsg = 0.f, lsb = 0.f, lsd = 0.f, lsa = 0.f;
#pragma unroll
    for (int c = 0; c < 4; c++) {
        int i = 4 * s + c;
        float t = t_c[c];
        float dist = (i < 63) ? 0.06349206715822f : 1e10f;  // fl(4/63)
        float dens2 = softplus_lg2(fmaf(t, bd, ad));
        float e = ex2(-dens2 * dist);
        float a = 1.0f - e;
        float f = e + 1e-10f;
        float wl = a * trans_l;
        localw[c] = wl;
        float tr = tanh_approx(fmaf(t, bch[0], ach[0]));
        float tg = tanh_approx(fmaf(t, bch[1], ach[1]));
        float tb = tanh_approx(fmaf(t, bch[2], ach[2]));
        lsr += wl * tr; lsg += wl * tg; lsb += wl * tb;
        lsd += wl * t;  lsa += wl;
        trans_l *= f;
    }
    // segmented exclusive product scan of per-lane transmittance
    float S = trans_l;
#pragma unroll
    for (int d = 1; d < 16; d <<= 1) {
        float v = __shfl_up_sync(FULL, S, d, 16);
        if (s >= d) S *= v;
    }
    float E = __shfl_up_sync(FULL, S, 1, 16);
    if (s == 0) E = 1.0f;

    float sr = seg_red_sum(E * lsr);
    float sg = seg_red_sum(E * lsg);
    float sb = seg_red_sum(E * lsb);
    float sd = seg_red_sum(E * lsd);
    float sa = seg_red_sum(E * lsa);

    // ---- CDF ----
    float ps0 = E * localw[0] + 1e-5f;
    float ps1 = ps0 + (E * localw[1] + 1e-5f);
    float ps2 = ps1 + (E * localw[2] + 1e-5f);
    float ps3 = ps2 + (E * localw[3] + 1e-5f);
    float Ss = ps3;
#pragma unroll
    for (int d = 1; d < 16; d <<= 1) {
        float v = __shfl_up_sync(FULL, Ss, d, 16);
        if (s >= d) Ss += v;
    }
    float Es = __shfl_up_sync(FULL, Ss, 1, 16);
    if (s == 0) Es = 0.0f;
    float total = __shfl_sync(FULL, Ss, 15, 16);
    float inv_total = __fdividef(1.0f, total);
    if (s == 0) cdf[0] = 0.0f;
    cdf[4 * s + 1] = (Es + ps0) * inv_total;
    cdf[4 * s + 2] = (Es + ps1) * inv_total;
    cdf[4 * s + 3] = (Es + ps2) * inv_total;
    cdf[4 * s + 4] = (Es + ps3) * inv_total;
    __syncwarp();

    // ---- inverse-CDF importance sampling (4 u's / lane) ----
    float tsv[4];
#pragma unroll
    for (int c = 0; c < 4; c++) {
        int k = 4 * s + c;
        float u = u_of(k);
        int idx = 1 + cnt64_le(cdf + 1, u);   // in [1,65]
        int b = idx - 1;
        float cdf0 = cdf[min(b, 64)];
        float cdf1 = cdf[min(idx, 64)];
        float denom = cdf1 - cdf0;
        if (denom < 1e-5f) denom = 1.0f;
        float tt = __fdividef(u - cdf0, denom);
        // idx<=63: bin0=ta[b], bin1=ta[idx], slope within 1 ulp of 4/63.
        // idx>=64: both bins clamp to ta[63]=6 -> value is exactly 6.
        float v = (idx <= 63) ? fmaf(tt, 0.06349206715822f, t_of_i(b)) : 6.0f;
        tsv[c] = v;
        ts[k] = v;
    }
    __syncwarp();

    // ---- merge ranks (exact comparisons on stored floats) -> scatter to ft ----
#pragma unroll
    for (int c = 0; c < 4; c++) {
        int j = 4 * s + c;
        float av = t_c[c];
        ft[j + cnt64_lt(ts, av)] = av;      // a before equal b
        float bv = tsv[c];
        ft[j + cnt_ta_le(bv)] = bv;
    }
    __syncwarp();

    // ========= FINE PASS: 8 samples/lane, local-accumulate =========
    const float4 q1 = *reinterpret_cast<const float4*>(&ft[8 * s]);
    const float4 q2 = *reinterpret_cast<const float4*>(&ft[8 * s + 4]);
    const float t9 = ft[8 * s + 8];   // s==15: garbage, guarded by i<127
    float tf[9] = {q1.x, q1.y, q1.z, q1.w, q2.x, q2.y, q2.z, q2.w, t9};

    float ltr = 1.0f;
    float lfr = 0.f, lfg = 0.f, lfb = 0.f, lfd = 0.f, lfa = 0.f;
#pragma unroll
    for (int c = 0; c < 8; c++) {
        int i = 8 * s + c;
        float t = tf[c];
        float dist = (i < 127) ? (tf[c + 1] - t) : 1e10f;
        float dens2 = softplus_lg2(fmaf(t, bd, ad));
        float e = ex2(-dens2 * dist);
        float a = 1.0f - e;
        float f = e + 1e-10f;
        float wl = a * ltr;
        float tr = tanh_approx(fmaf(t, bch[0], ach[0]));
        float tg = tanh_approx(fmaf(t, bch[1], ach[1]));
        float tb = tanh_approx(fmaf(t, bch[2], ach[2]));
        lfr += wl * tr; lfg += wl * tg; lfb += wl * tb;
        lfd += wl * t;  lfa += wl;
        ltr *= f;
    }
    float Sf = ltr;
#pragma unroll
    for (int d = 1; d < 16; d <<= 1) {
        float v = __shfl_up_sync(FULL, Sf, d, 16);
        if (s >= d) Sf *= v;
    }
    float Ef = __shfl_up_sync(FULL, Sf, 1, 16);
    if (s == 0) Ef = 1.0f;

    float fsr = seg_red_sum(Ef * lfr);
    float fsg = seg_red_sum(Ef * lfg);
    float fsb = seg_red_sum(Ef * lfb);
    float fsd = seg_red_sum(Ef * lfd);
    float fsa = seg_red_sum(Ef * lfa);

    // ---- outputs: rgb(3N), depth(N), acc(N), frgb(3N), fdepth(N), facc(N) ----
    // color_out = 0.5*(sum_wl_tanh - acc) + 1  (folds sigmoid affine + white bg)
    if (s == 0) {
        const int N = NRAYS;
        out[3 * ray + 0] = fmaf(0.5f, sr - sa, 1.0f);
        out[3 * ray + 1] = fmaf(0.5f, sg - sa, 1.0f);
        out[3 * ray + 2] = fmaf(0.5f, sb - sa, 1.0f);
        out[3 * N + ray] = sd;
        out[4 * N + ray] = sa;
        out[5 * N + 3 * ray + 0] = fmaf(0.5f, fsr - fsa, 1.0f);
        out[5 * N + 3 * ray + 1] = fmaf(0.5f, fsg - fsa, 1.0f);
        out[5 * N + 3 * ray + 2] = fmaf(0.5f, fsb - fsa, 1.0f);
        out[8 * N + ray] = fsd;
        out[9 * N + ray] = fsa;
    }
}

extern "C" void kernel_launch(void* const* d_in, const int* in_sizes, int n_in,
                              void* d_out, int out_size) {
    const float* ro = nullptr;
    const float* rd = nullptr;
    const float* Wd = nullptr;
    const float* Wc = nullptr;
    for (int i = 0; i < n_in; i++) {
        int sz = in_sizes[i];
        if (sz == 3) Wd = (const float*)d_in[i];
        else if (sz == 9) Wc = (const float*)d_in[i];
        else if (sz == 3 * NRAYS) {
            if (!ro) ro = (const float*)d_in[i];
            else if (!rd) rd = (const float*)d_in[i];
        }
    }
    vr_kernel<<<NRAYS / RPB, 256>>>(ro, rd, Wd, Wc, (float*)d_out);
}

// round 17
// speedup vs baseline: 1.2427x; 1.1239x over previous
#include <cuda_runtime.h>

#define NRAYS 131072
#define RPB 16           // rays per block (2 per warp, 16-lane segments)
#define FULL 0xffffffffu

__device__ __forceinline__ float tanh_approx(float x) {
    float y;
    asm("tanh.approx.f32 %0, %1;" : "=f"(y) : "f"(x));
    return y;
}
__device__ __forceinline__ float ex2(float x) {
    float y;
    asm("ex2.approx.f32 %0, %1;" : "=f"(y) : "f"(x));
    return y;
}
// dens2 = softplus(x)*log2e = log2(1+e^x); max() form is tail-safe (see R15/16)
__device__ __forceinline__ float softplus_lg2(float x) {
    float y = __expf(-fabsf(x));
    float cand = y * fmaf(y, -0.72134752f, 1.44269504f);
    float big = __log2f(1.0f + y);
    float l2 = fmaxf(big, cand);
    return fmaf(fmaxf(x, 0.0f), 1.44269504f, l2);
}
// coarse grid value: unconditional form is bit-identical to the guarded
// linspace for all i in [0,63] (fl(63*fl(1/63)) rounds to exactly 1.0f)
__device__ __forceinline__ float t_of_i(int i) {
    return fmaf(4.0f, (float)i * (1.0f / 63.0f), 2.0f);
}
__device__ __forceinline__ float u_of(int k) {
    return (float)k * (1.0f / 63.0f);
}

// count of c[i] <= u over exactly 64 sorted entries (result in [0,64])
__device__ __forceinline__ int cnt64_le(const float* c, float u) {
    if (c[63] <= u) return 64;
    int pos = 0;
#pragma unroll
    for (int step = 32; step >= 1; step >>= 1)
        if (c[pos + step - 1] <= u) pos += step;
    return pos;
}
// count of {i in [0,64): t_of_i(i) <= v}  -- analytic guess + exact correction
// (exact: compares against the true t_of_i floats)
__device__ __forceinline__ int cnt_ta_le(float v) {
    float g = fmaf(v, 15.75f, -31.5f);     // (v-2)*63/4
    int c = (int)floorf(g) + 1;
    c = min(64, max(0, c));
    if (c < 64 && t_of_i(c) <= v) c++;
    if (c < 64 && t_of_i(c) <= v) c++;
    if (c > 0 && t_of_i(c - 1) > v) c--;
    if (c > 0 && t_of_i(c - 1) > v) c--;
    return c;
}
// reduce-sum within a 16-lane segment (xor d<16 never crosses segments)
__device__ __forceinline__ float seg_red_sum(float x) {
#pragma unroll
    for (int d = 8; d >= 1; d >>= 1) x += __shfl_xor_sync(FULL, x, d);
    return x;
}

__global__ void __launch_bounds__(256, 6) vr_kernel(
    const float* __restrict__ ro, const float* __restrict__ rd,
    const float* __restrict__ Wd, const float* __restrict__ Wc,
    float* __restrict__ out)
{
    const int tid = threadIdx.x;
    const int s = tid & 15;              // sub-lane within segment
    const int seg = tid >> 4;            // segment (ray) index within block
    const int ray = blockIdx.x * RPB + seg;

    __shared__ float s_cdf[RPB][65];
    __shared__ int   s_cnt[RPB][65];     // histogram of b-ranks r_k
    __shared__ __align__(16) float s_ft[RPB][132];

    float* cdf = s_cdf[seg];
    int* C = s_cnt[seg];
    float* ft = s_ft[seg];

    // ---- per-ray precompute: pos @ W = (ro.W) + t*(rd.W) ----
    const float ox = ro[3 * ray + 0], oy = ro[3 * ray + 1], oz = ro[3 * ray + 2];
    const float dx = rd[3 * ray + 0], dy = rd[3 * ray + 1], dz = rd[3 * ray + 2];
    const float wd0 = __ldg(&Wd[0]), wd1 = __ldg(&Wd[1]), wd2 = __ldg(&Wd[2]);
    const float ad = ox * wd0 + oy * wd1 + oz * wd2;
    const float bd = dx * wd0 + dy * wd1 + dz * wd2;
    float ach[3], bch[3];   // PRE-HALVED color coefficients for tanh-sigmoid
#pragma unroll
    for (int k = 0; k < 3; k++) {
        float w0 = __ldg(&Wc[k]), w1 = __ldg(&Wc[3 + k]), w2 = __ldg(&Wc[6 + k]);
        ach[k] = 0.5f * (ox * w0 + oy * w1 + oz * w2);
        bch[k] = 0.5f * (dx * w0 + dy * w1 + dz * w2);
    }

    // ========= COARSE PASS: 4 samples/lane, local-accumulate =========
    float t_c[4], localw[4];
#pragma unroll
    for (int c = 0; c < 4; c++) t_c[c] = t_of_i(4 * s + c);
    float trans_l = 1.0f;
    float lsr = 0.f, lsg = 0.f, lsb = 0.f, lsd = 0.f, lsa = 0.f;
#pragma unroll
    for (int c = 0; c < 4; c++) {
        int i = 4 * s + c;
        float t = t_c[c];
        float dist = (i < 63) ? 0.06349206715822f : 1e10f;  // fl(4/63)
        float dens2 = softplus_lg2(fmaf(t, bd, ad));
        float e = ex2(-dens2 * dist);
        float a = 1.0f - e;
        float f = e + 1e-10f;
        float wl = a * trans_l;
        localw[c] = wl;
        float tr = tanh_approx(fmaf(t, bch[0], ach[0]));
        float tg = tanh_approx(fmaf(t, bch[1], ach[1]));
        float tb = tanh_approx(fmaf(t, bch[2], ach[2]));
        lsr += wl * tr; lsg += wl * tg; lsb += wl * tb;
        lsd += wl * t;  lsa += wl;
        trans_l *= f;
    }
    // segmented exclusive product scan of per-lane transmittance
    float S = trans_l;
#pragma unroll
    for (int d = 1; d < 16; d <<= 1) {
        float v = __shfl_up_sync(FULL, S, d, 16);
        if (s >= d) S *= v;
    }
    float E = __shfl_up_sync(FULL, S, 1, 16);
    if (s == 0) E = 1.0f;

    float sr = seg_red_sum(E * lsr);
    float sg = seg_red_sum(E * lsg);
    float sb = seg_red_sum(E * lsb);
    float sd = seg_red_sum(E * lsd);
    float sa = seg_red_sum(E * lsa);

    // ---- CDF ----
    float ps0 = E * localw[0] + 1e-5f;
    float ps1 = ps0 + (E * localw[1] + 1e-5f);
    float ps2 = ps1 + (E * localw[2] + 1e-5f);
    float ps3 = ps2 + (E * localw[3] + 1e-5f);
    float Ss = ps3;
#pragma unroll
    for (int d = 1; d < 16; d <<= 1) {
        float v = __shfl_up_sync(FULL, Ss, d, 16);
        if (s >= d) Ss += v;
    }
    float Es = __shfl_up_sync(FULL, Ss, 1, 16);
    if (s == 0) Es = 0.0f;
    float total = __shfl_sync(FULL, Ss, 15, 16);
    float inv_total = __fdividef(1.0f, total);
    if (s == 0) { cdf[0] = 0.0f; C[64] = 0; }
    cdf[4 * s + 1] = (Es + ps0) * inv_total;
    cdf[4 * s + 2] = (Es + ps1) * inv_total;
    cdf[4 * s + 3] = (Es + ps2) * inv_total;
    cdf[4 * s + 4] = (Es + ps3) * inv_total;
    // zero the rank histogram (covered by the same syncwarp)
#pragma unroll
    for (int c = 0; c < 4; c++) C[4 * s + c] = 0;
    __syncwarp();

    // ---- inverse-CDF sampling + b-scatter + rank histogram ----
#pragma unroll
    for (int c = 0; c < 4; c++) {
        int k = 4 * s + c;
        float u = u_of(k);
        int idx = 1 + cnt64_le(cdf + 1, u);   // in [1,65]
        int b = idx - 1;
        float cdf0 = cdf[min(b, 64)];
        float cdf1 = cdf[min(idx, 64)];
        float denom = cdf1 - cdf0;
        if (denom < 1e-5f) denom = 1.0f;
        float tt = __fdividef(u - cdf0, denom);
        // idx<=63: interp with slope 4/63 from ta[b]; idx>=64: exactly 6.0
        float v = (idx <= 63) ? fmaf(tt, 0.06349206715822f, t_of_i(b)) : 6.0f;
        int r = cnt_ta_le(v);                  // b-rank among coarse points
        ft[k + r] = v;                         // b scatter (b after equal a)
        atomicAdd(&C[r], 1);                   // histogram for a-ranks
    }
    __syncwarp();

    // ---- a-ranks by counting scan: P[j] = #{k: r_k <= j} ----
    // (exact integer identity: #{ts_k < ta_j} == #{r_k <= j}, ta strictly inc.)
    int c0 = C[4 * s + 0], c1 = C[4 * s + 1], c2 = C[4 * s + 2], c3 = C[4 * s + 3];
    int l0 = c0, l1 = l0 + c1, l2 = l1 + c2, l3 = l2 + c3;
    int Sc = l3;
#pragma unroll
    for (int d = 1; d < 16; d <<= 1) {
        int v = __shfl_up_sync(FULL, Sc, d, 16);
        if (s >= d) Sc += v;
    }
    int Ec = __shfl_up_sync(FULL, Sc, 1, 16);
    if (s == 0) Ec = 0;
    // a scatter: position = j + P[j]
    ft[4 * s + 0 + Ec + l0] = t_c[0];
    ft[4 * s + 1 + Ec + l1] = t_c[1];
    ft[4 * s + 2 + Ec + l2] = t_c[2];
    ft[4 * s + 3 + Ec + l3] = t_c[3];
    __syncwarp();

    // ========= FINE PASS: 8 samples/lane, local-accumulate =========
    const float4 q1 = *reinterpret_cast<const float4*>(&ft[8 * s]);
    const float4 q2 = *reinterpret_cast<const float4*>(&ft[8 * s + 4]);
    const float t9 = ft[8 * s + 8];   // s==15: garbage, guarded by i<127
    float tf[9] = {q1.x, q1.y, q1.z, q1.w, q2.x, q2.y, q2.z, q2.w, t9};

    float ltr = 1.0f;
    float lfr = 0.f, lfg = 0.f, lfb = 0.f, lfd = 0.f, lfa = 0.f;
#pragma unroll
    for (int c = 0; c < 8; c++) {
        int i = 8 * s + c;
        float t = tf[c];
        float dist = (i < 127) ? (tf[c + 1] - t) : 1e10f;
        float dens2 = softplus_lg2(fmaf(t, bd, ad));
        float e = ex2(-dens2 * dist);
        float a = 1.0f - e;
        float f = e + 1e-10f;
        float wl = a * ltr;
        float tr = tanh_approx(fmaf(t, bch[0], ach[0]));
        float tg = tanh_approx(fmaf(t, bch[1], ach[1]));
        float tb = tanh_approx(fmaf(t, bch[2], ach[2]));
        lfr += wl * tr; lfg += wl * tg; lfb += wl * tb;
        lfd += wl * t;  lfa += wl;
        ltr *= f;
    }
    float Sf = ltr;
#pragma unroll
    for (int d = 1; d < 16; d <<= 1) {
        float v = __shfl_up_sync(FULL, Sf, d, 16);
        if (s >= d) Sf *= v;
    }
    float Ef = __shfl_up_sync(FULL, Sf, 1, 16);
    if (s == 0) Ef = 1.0f;

    float fsr = seg_red_sum(Ef * lfr);
    float fsg = seg_red_sum(Ef * lfg);
    float fsb = seg_red_sum(Ef * lfb);
    float fsd = seg_red_sum(Ef * lfd);
    float fsa = seg_red_sum(Ef * lfa);

    // ---- outputs: rgb(3N), depth(N), acc(N), frgb(3N), fdepth(N), facc(N) ----
    if (s == 0) {
        const int N = NRAYS;
        out[3 * ray + 0] = fmaf(0.5f, sr - sa, 1.0f);
        out[3 * ray + 1] = fmaf(0.5f, sg - sa, 1.0f);
        out[3 * ray + 2] = fmaf(0.5f, sb - sa, 1.0f);
        out[3 * N + ray] = sd;
        out[4 * N + ray] = sa;
        out[5 * N + 3 * ray + 0] = fmaf(0.5f, fsr - fsa, 1.0f);
        out[5 * N + 3 * ray + 1] = fmaf(0.5f, fsg - fsa, 1.0f);
        out[5 * N + 3 * ray + 2] = fmaf(0.5f, fsb - fsa, 1.0f);
        out[8 * N + ray] = fsd;
        out[9 * N + ray] = fsa;
    }
}

extern "C" void kernel_launch(void* const* d_in, const int* in_sizes, int n_in,
                              void* d_out, int out_size) {
    const float* ro = nullptr;
    const float* rd = nullptr;
    const float* Wd = nullptr;
    const float* Wc = nullptr;
    for (int i = 0; i < n_in; i++) {
        int sz = in_sizes[i];
        if (sz == 3) Wd = (const float*)d_in[i];
        else if (sz == 9) Wc = (const float*)d_in[i];
        else if (sz == 3 * NRAYS) {
            if (!ro) ro = (const float*)d_in[i];
            else if (!rd) rd = (const float*)d_in[i];
        }
    }
    vr_kernel<<<NRAYS / RPB, 256>>>(ro, rd, Wd, Wc, (float*)d_out);
}